// round 10
// baseline (speedup 1.0000x reference)
#include <cuda_runtime.h>
#include <math.h>

// ---------------------------------------------------------------------------
// SelectiveModel: B=32768, T=23, H=64, SLOTS=8, VOCAB=64.
//
// Structural collapse: gating MLP -> S[64][64] sigmoid table (recurrence is
// pure integer state); readout L1 -> QP/MP tables; only the 64x64 L2 GEMM
// remains as real FP work.
//
// R10: R9 with a re-tiled gemm:
//   gemm: 128 thr/block, 64 batches; warp 16b x 64c; thread 4b x 8c ->
//         16 FFMA2 per 3 LDS per k (2x better ratio), launch_bounds(128,4)
//         so ptxas can pipeline k-loop loads (R9 was reg-strangled at 61).
//   p0/p1/rh unchanged from R9.
// ---------------------------------------------------------------------------

#define BTOT 32768

__device__ float g_S  [64 * 64];
__device__ float g_QP [66 * 68];
__device__ float g_MP [64 * 68];
__device__ float g_ED [64 * 32];     // edot[c][j]
__device__ float g_MDT[32 * 64];     // mdot transposed [j][m]
__device__ float g_HT [64 * BTOT];   // k-major h

// ---------------- packed fp32x2 helpers -------------------------------------
__device__ __forceinline__ unsigned long long pk2(float lo, float hi) {
    unsigned long long r;
    asm("mov.b64 %0, {%1, %2};" : "=l"(r) : "f"(lo), "f"(hi));
    return r;
}
__device__ __forceinline__ void upk2(unsigned long long v, float& lo, float& hi) {
    asm("mov.b64 {%0, %1}, %2;" : "=f"(lo), "=f"(hi) : "l"(v));
}
__device__ __forceinline__ void fma2(unsigned long long& d,
                                     unsigned long long a, unsigned long long b) {
    asm("fma.rn.f32x2 %0, %1, %2, %0;" : "+l"(d) : "l"(a), "l"(b));
}

// ===================== P0: all independent dot products =====================
__global__ void p0_kernel(
    const float* __restrict__ embed, const float* __restrict__ gw1,
    const float* __restrict__ rw1,   const float* __restrict__ rb1)
{
    const int idx = blockIdx.x * 256 + threadIdx.x;
    if (idx < 4096) {
        const int r = idx >> 5, j = idx & 31;
        const float* e = embed + (r & 63) * 64;
        const float* w = gw1 + ((r >> 6) * 64) * 32 + j;
        float acc[4] = {0.f, 0.f, 0.f, 0.f};
        #pragma unroll
        for (int k0 = 0; k0 < 64; k0 += 8) {
            float wr[8], er[8];
            #pragma unroll
            for (int i = 0; i < 8; i++) { wr[i] = w[(k0 + i) * 32]; er[i] = e[k0 + i]; }
            #pragma unroll
            for (int i = 0; i < 8; i++) acc[i & 3] += er[i] * wr[i];
        }
        const float v = (acc[0] + acc[1]) + (acc[2] + acc[3]);
        if (r < 64) g_ED[r * 32 + j] = v;
        else        g_MDT[j * 64 + (r - 64)] = v;
    } else if (idx < 8320) {
        const int e2 = idx - 4096;
        const int r = e2 >> 6, j = e2 & 63;
        const float* e = embed + r * 64;
        const float* w = rw1 + j;
        float acc[4] = {rb1[j], 0.f, 0.f, 0.f};
        #pragma unroll
        for (int k0 = 0; k0 < 64; k0 += 8) {
            float wr[8], er[8];
            #pragma unroll
            for (int i = 0; i < 8; i++) { wr[i] = w[(k0 + i) * 64]; er[i] = e[k0 + i]; }
            #pragma unroll
            for (int i = 0; i < 8; i++) acc[i & 3] += er[i] * wr[i];
        }
        g_QP[r * 68 + j] = (acc[0] + acc[1]) + (acc[2] + acc[3]);
        if (j < 4) g_QP[r * 68 + 64 + j] = 0.f;
    } else if (idx < 12416) {
        const int e2 = idx - 8320;
        const int r = e2 >> 6, j = e2 & 63;
        const float* e = embed + r * 64;
        const float* w = rw1 + 64 * 64 + j;
        float acc[4] = {0.f, 0.f, 0.f, 0.f};
        #pragma unroll
        for (int k0 = 0; k0 < 64; k0 += 8) {
            float wr[8], er[8];
            #pragma unroll
            for (int i = 0; i < 8; i++) { wr[i] = w[(k0 + i) * 64]; er[i] = e[k0 + i]; }
            #pragma unroll
            for (int i = 0; i < 8; i++) acc[i & 3] += er[i] * wr[i];
        }
        g_MP[r * 68 + j] = (acc[0] + acc[1]) + (acc[2] + acc[3]);
        if (j < 4) g_MP[r * 68 + 64 + j] = 0.f;
    }
}

// ===================== P1: S table combine + sigmoid ========================
__global__ void p1_kernel(
    const float* __restrict__ gb1, const float* __restrict__ gw2,
    const float* __restrict__ gb2)
{
    const int idx = blockIdx.x * 128 + threadIdx.x;
    const int c = idx >> 6, m = idx & 63;
    const float* ed = g_ED + c * 32;
    float acc = gb2[0];
    #pragma unroll
    for (int j0 = 0; j0 < 32; j0 += 8) {
        float md[8], edv[8], gb[8], gw[8];
        #pragma unroll
        for (int i = 0; i < 8; i++) {
            md[i]  = g_MDT[(j0 + i) * 64 + m];
            edv[i] = ed[j0 + i];
            gb[i]  = gb1[j0 + i];
            gw[i]  = gw2[j0 + i];
        }
        #pragma unroll
        for (int i = 0; i < 8; i++)
            acc += fmaxf(edv[i] + md[i] + gb[i], 0.f) * gw[i];
    }
    g_S[c * 64 + m] = 1.f / (1.f + expf(-acc));
}

// ====================== rh: fused recurrence + h gather =====================
// grid 512 x 256; block = 64 batches. Unchanged from R9.
#define RH_SMEM_BYTES ((64 * 65 + 66 * 68 + 64 * 68) * 4 + 64 * 24)

__global__ void __launch_bounds__(256, 4) rh_kernel(
    const int* __restrict__ seqs32, const int* __restrict__ qtok32)
{
    extern __shared__ float sm[];
    float* sS  = sm;                       // [64][65]
    float* sQP = sS + 64 * 65;             // [66][68]
    float* sMP = sQP + 66 * 68;            // [64][68]
    unsigned char* sTok = (unsigned char*)(sMP + 64 * 68);
    const int tid = threadIdx.x, bid = blockIdx.x;

    // int64 vs int32 token dtype detection (odd LE words of small int64 == 0)
    const int oddOr = seqs32[1] | seqs32[3] | seqs32[5] | seqs32[7] |
                      seqs32[9] | seqs32[11] | seqs32[13] | seqs32[15];
    const bool is64 = (oddOr == 0);

    for (int i = tid; i < 4096; i += 256)
        sS[(i >> 6) * 65 + (i & 63)] = g_S[i];
    {
        const float4* g = (const float4*)g_QP; float4* s = (float4*)sQP;
        for (int i = tid; i < 1122; i += 256) s[i] = g[i];
        g = (const float4*)g_MP; s = (float4*)sMP;
        for (int i = tid; i < 1088; i += 256) s[i] = g[i];
    }
    {
        const int base = bid * 64 * 24;
        for (int i = tid; i < 64 * 24; i += 256) {
            const int v = is64 ? seqs32[2 * (base + i)] : seqs32[base + i];
            sTok[i] = (unsigned char)v;
        }
    }
    const int jq = tid & 3;                // j-quarter: adjacent lanes differ
    const int bl = tid >> 2;               // local batch 0..63
    const int b  = bid * 64 + bl;
    const int qt = is64 ? qtok32[2 * b] : qtok32[b];
    __syncthreads();

    // ---- recurrence (integer-key argmax; validated R4-R9) ----
    int moff[8];
    {
        const unsigned char* myTok = sTok + bl * 24;
        int mt[8];
        #pragma unroll
        for (int s = 0; s < 8; s++) mt[s] = myTok[s];
        #pragma unroll
        for (int t = 8; t < 23; t++) {
            const int c = myTok[t];
            const float* Srow = sS + c * 65;
            unsigned key[8];
            #pragma unroll
            for (int s = 0; s < 8; s++) {
                const unsigned bits = __float_as_uint(Srow[mt[s]]);
                key[s] = (bits << 2) | (unsigned)(3 - (s & 3));
            }
            const unsigned a0 = max(max(key[0], key[1]), max(key[2], key[3]));
            const unsigned a1 = max(max(key[4], key[5]), max(key[6], key[7]));
            const int bi = ((a1 >> 2) > (a0 >> 2)) ? (4 + 3 - (int)(a1 & 3))
                                                   : (3 - (int)(a0 & 3));
            #pragma unroll
            for (int s = 0; s < 8; s++) if (bi == s) mt[s] = c;
        }
        #pragma unroll
        for (int s = 0; s < 8; s++) moff[s] = mt[s] * 68 + jq * 16;
    }

    // ---- h gather: this thread's 16 j's ----
    unsigned long long h[8];
    {
        const float* qp = sQP + qt * 68 + jq * 16;
        #pragma unroll
        for (int i = 0; i < 4; i++) {
            const ulonglong2 q = *(const ulonglong2*)(qp + 4 * i);
            h[2 * i] = q.x; h[2 * i + 1] = q.y;
        }
    }
    const unsigned long long E2 = pk2(0.125f, 0.125f);
    #pragma unroll
    for (int s = 0; s < 8; s++) {
        const float* mp = sMP + moff[s];
        #pragma unroll
        for (int i = 0; i < 4; i++) {
            const ulonglong2 m = *(const ulonglong2*)(mp + 4 * i);
            fma2(h[2 * i],     m.x, E2);
            fma2(h[2 * i + 1], m.y, E2);
        }
    }
    // relu + k-major store; each (row, 8-consecutive-batch) = full 32B sector
    float* ht = g_HT + (jq * 16) * BTOT + b;
    #pragma unroll
    for (int i = 0; i < 8; i++) {
        float lo, hi; upk2(h[i], lo, hi);
        ht[(2 * i)     * BTOT] = fmaxf(lo, 0.f);
        ht[(2 * i + 1) * BTOT] = fmaxf(hi, 0.f);
    }
}

// ============================ gemm: HT @ rw2 + rb2 ==========================
// grid 512 x 128; block tile 64b x 64c; warp 16b x 64c; thread 4b x 8c.
// 16 FFMA2 per 3 LDS per k; launch_bounds(128,4) -> <=128 regs for k-loop
// load hoisting.
#define GEMM_SMEM_BYTES ((64 * 68 * 2 + 64) * 4)

__global__ void __launch_bounds__(128, 4) gemm_kernel(
    const float* __restrict__ rw2, const float* __restrict__ rb2,
    float* __restrict__ out)
{
    extern __shared__ float sm[];
    float* sHT = sm;                 // [64 k][68] (64 batches, padded)
    float* sW  = sm + 64 * 68;       // [64 k][68] (64 cols, padded)
    float* sRB = sW + 64 * 68;       // [64]
    const int tid = threadIdx.x, bid = blockIdx.x;
    const int b0 = bid * 64;

    for (int i = tid; i < 1024; i += 128) {
        const int r = i >> 4, c4 = i & 15;
        *(float4*)(sHT + r * 68 + c4 * 4) =
            *(const float4*)(g_HT + r * BTOT + b0 + c4 * 4);
        ((float4*)sW)[r * 17 + c4] = ((const float4*)rw2)[i];
    }
    if (tid < 16) ((float4*)sRB)[tid] = ((const float4*)rb2)[tid];
    __syncthreads();

    const int w = tid >> 5, lane = tid & 31;
    const int bg = lane >> 3;            // batch sub-group (0..3)
    const int cg = lane & 7;             // col group (0..7)
    const float* hrow = sHT + w * 16 + bg * 4;    // + k*68
    const float* wcol = sW + cg * 8;              // + k*68

    unsigned long long acc[16];          // 4 batches x 4 col-pairs
    {
        const ulonglong2 r0 = *(const ulonglong2*)(sRB + cg * 8);
        const ulonglong2 r1 = *(const ulonglong2*)(sRB + cg * 8 + 4);
        #pragma unroll
        for (int bb = 0; bb < 4; bb++) {
            acc[bb * 4 + 0] = r0.x; acc[bb * 4 + 1] = r0.y;
            acc[bb * 4 + 2] = r1.x; acc[bb * 4 + 3] = r1.y;
        }
    }
    #pragma unroll 8
    for (int k = 0; k < 64; k++) {
        const float4 hv     = *(const float4*)(hrow + k * 68);
        const ulonglong2 wA = *(const ulonglong2*)(wcol + k * 68);
        const ulonglong2 wB = *(const ulonglong2*)(wcol + k * 68 + 4);
        unsigned long long hb;
        hb = pk2(hv.x, hv.x);
        fma2(acc[0],  hb, wA.x); fma2(acc[1],  hb, wA.y);
        fma2(acc[2],  hb, wB.x); fma2(acc[3],  hb, wB.y);
        hb = pk2(hv.y, hv.y);
        fma2(acc[4],  hb, wA.x); fma2(acc[5],  hb, wA.y);
        fma2(acc[6],  hb, wB.x); fma2(acc[7],  hb, wB.y);
        hb = pk2(hv.z, hv.z);
        fma2(acc[8],  hb, wA.x); fma2(acc[9],  hb, wA.y);
        fma2(acc[10], hb, wB.x); fma2(acc[11], hb, wB.y);
        hb = pk2(hv.w, hv.w);
        fma2(acc[12], hb, wA.x); fma2(acc[13], hb, wA.y);
        fma2(acc[14], hb, wB.x); fma2(acc[15], hb, wB.y);
    }

    const int gb0 = b0 + w * 16 + bg * 4;
    #pragma unroll
    for (int bb = 0; bb < 4; bb++) {
        float* op = out + (gb0 + bb) * 64 + cg * 8;
        float4 v0, v1;
        upk2(acc[bb * 4 + 0], v0.x, v0.y); upk2(acc[bb * 4 + 1], v0.z, v0.w);
        upk2(acc[bb * 4 + 2], v1.x, v1.y); upk2(acc[bb * 4 + 3], v1.z, v1.w);
        *(float4*)op = v0;
        *(float4*)(op + 4) = v1;
    }
}

// ============================== launch ======================================
extern "C" void kernel_launch(void* const* d_in, const int* in_sizes, int n_in,
                              void* d_out, int out_size)
{
    const int*   seqs  = (const int*)  d_in[0];
    const int*   qtok  = (const int*)  d_in[1];
    const float* embed = (const float*)d_in[2];
    const float* gw1   = (const float*)d_in[3];
    const float* gb1   = (const float*)d_in[4];
    const float* gw2   = (const float*)d_in[5];
    const float* gb2   = (const float*)d_in[6];
    const float* rw1   = (const float*)d_in[7];
    const float* rb1   = (const float*)d_in[8];
    const float* rw2   = (const float*)d_in[9];
    const float* rb2   = (const float*)d_in[10];

    cudaFuncSetAttribute(rh_kernel,
                         cudaFuncAttributeMaxDynamicSharedMemorySize,
                         RH_SMEM_BYTES);
    cudaFuncSetAttribute(gemm_kernel,
                         cudaFuncAttributeMaxDynamicSharedMemorySize,
                         GEMM_SMEM_BYTES);

    p0_kernel<<<49, 256>>>(embed, gw1, rw1, rb1);
    p1_kernel<<<32, 128>>>(gb1, gw2, gb2);
    rh_kernel<<<512, 256, RH_SMEM_BYTES>>>(seqs, qtok);
    gemm_kernel<<<512, 128, GEMM_SMEM_BYTES>>>(rw2, rb2, (float*)d_out);
}

// round 11
// speedup vs baseline: 1.1187x; 1.1187x over previous
#include <cuda_runtime.h>
#include <math.h>

// ---------------------------------------------------------------------------
// SelectiveModel: B=32768, T=23, H=64, SLOTS=8, VOCAB=64.
//
// Structural collapse: gating MLP -> S[64][64] sigmoid table (recurrence is
// pure integer state); readout L1 -> QP/MP tables; only the 64x64 L2 GEMM
// remains as real FP work.
//
// R11:
//   gemm: R9 tiling (256 thr, 64b/block, thread 4b x 4c) + explicit software
//         pipeline (preload k+1 before k's FFMA2s), (256,3) for 84 regs.
//   rh  : 128 batches/block (512 thr, grid 256) -> halved table staging.
//   p0/p1 unchanged.
// ---------------------------------------------------------------------------

#define BTOT 32768

__device__ float g_S  [64 * 64];
__device__ float g_QP [66 * 68];
__device__ float g_MP [64 * 68];
__device__ float g_ED [64 * 32];     // edot[c][j]
__device__ float g_MDT[32 * 64];     // mdot transposed [j][m]
__device__ float g_HT [64 * BTOT];   // k-major h

// ---------------- packed fp32x2 helpers -------------------------------------
__device__ __forceinline__ unsigned long long pk2(float lo, float hi) {
    unsigned long long r;
    asm("mov.b64 %0, {%1, %2};" : "=l"(r) : "f"(lo), "f"(hi));
    return r;
}
__device__ __forceinline__ void upk2(unsigned long long v, float& lo, float& hi) {
    asm("mov.b64 {%0, %1}, %2;" : "=f"(lo), "=f"(hi) : "l"(v));
}
__device__ __forceinline__ void fma2(unsigned long long& d,
                                     unsigned long long a, unsigned long long b) {
    asm("fma.rn.f32x2 %0, %1, %2, %0;" : "+l"(d) : "l"(a), "l"(b));
}

// ===================== P0: all independent dot products =====================
__global__ void p0_kernel(
    const float* __restrict__ embed, const float* __restrict__ gw1,
    const float* __restrict__ rw1,   const float* __restrict__ rb1)
{
    const int idx = blockIdx.x * 256 + threadIdx.x;
    if (idx < 4096) {
        const int r = idx >> 5, j = idx & 31;
        const float* e = embed + (r & 63) * 64;
        const float* w = gw1 + ((r >> 6) * 64) * 32 + j;
        float acc[4] = {0.f, 0.f, 0.f, 0.f};
        #pragma unroll
        for (int k0 = 0; k0 < 64; k0 += 8) {
            float wr[8], er[8];
            #pragma unroll
            for (int i = 0; i < 8; i++) { wr[i] = w[(k0 + i) * 32]; er[i] = e[k0 + i]; }
            #pragma unroll
            for (int i = 0; i < 8; i++) acc[i & 3] += er[i] * wr[i];
        }
        const float v = (acc[0] + acc[1]) + (acc[2] + acc[3]);
        if (r < 64) g_ED[r * 32 + j] = v;
        else        g_MDT[j * 64 + (r - 64)] = v;
    } else if (idx < 8320) {
        const int e2 = idx - 4096;
        const int r = e2 >> 6, j = e2 & 63;
        const float* e = embed + r * 64;
        const float* w = rw1 + j;
        float acc[4] = {rb1[j], 0.f, 0.f, 0.f};
        #pragma unroll
        for (int k0 = 0; k0 < 64; k0 += 8) {
            float wr[8], er[8];
            #pragma unroll
            for (int i = 0; i < 8; i++) { wr[i] = w[(k0 + i) * 64]; er[i] = e[k0 + i]; }
            #pragma unroll
            for (int i = 0; i < 8; i++) acc[i & 3] += er[i] * wr[i];
        }
        g_QP[r * 68 + j] = (acc[0] + acc[1]) + (acc[2] + acc[3]);
        if (j < 4) g_QP[r * 68 + 64 + j] = 0.f;
    } else if (idx < 12416) {
        const int e2 = idx - 8320;
        const int r = e2 >> 6, j = e2 & 63;
        const float* e = embed + r * 64;
        const float* w = rw1 + 64 * 64 + j;
        float acc[4] = {0.f, 0.f, 0.f, 0.f};
        #pragma unroll
        for (int k0 = 0; k0 < 64; k0 += 8) {
            float wr[8], er[8];
            #pragma unroll
            for (int i = 0; i < 8; i++) { wr[i] = w[(k0 + i) * 64]; er[i] = e[k0 + i]; }
            #pragma unroll
            for (int i = 0; i < 8; i++) acc[i & 3] += er[i] * wr[i];
        }
        g_MP[r * 68 + j] = (acc[0] + acc[1]) + (acc[2] + acc[3]);
        if (j < 4) g_MP[r * 68 + 64 + j] = 0.f;
    }
}

// ===================== P1: S table combine + sigmoid ========================
__global__ void p1_kernel(
    const float* __restrict__ gb1, const float* __restrict__ gw2,
    const float* __restrict__ gb2)
{
    const int idx = blockIdx.x * 128 + threadIdx.x;
    const int c = idx >> 6, m = idx & 63;
    const float* ed = g_ED + c * 32;
    float acc = gb2[0];
    #pragma unroll
    for (int j0 = 0; j0 < 32; j0 += 8) {
        float md[8], edv[8], gb[8], gw[8];
        #pragma unroll
        for (int i = 0; i < 8; i++) {
            md[i]  = g_MDT[(j0 + i) * 64 + m];
            edv[i] = ed[j0 + i];
            gb[i]  = gb1[j0 + i];
            gw[i]  = gw2[j0 + i];
        }
        #pragma unroll
        for (int i = 0; i < 8; i++)
            acc += fmaxf(edv[i] + md[i] + gb[i], 0.f) * gw[i];
    }
    g_S[c * 64 + m] = 1.f / (1.f + expf(-acc));
}

// ====================== rh: fused recurrence + h gather =====================
// grid 256 x 512; block = 128 batches. jq = tid&3, bl = tid>>2 (adjacent-lane
// recurrence duplication -> smem broadcast). Per-thread code identical to R9.
#define RH_SMEM_BYTES ((64 * 65 + 66 * 68 + 64 * 68) * 4 + 128 * 24)

__global__ void __launch_bounds__(512, 2) rh_kernel(
    const int* __restrict__ seqs32, const int* __restrict__ qtok32)
{
    extern __shared__ float sm[];
    float* sS  = sm;                       // [64][65]
    float* sQP = sS + 64 * 65;             // [66][68]
    float* sMP = sQP + 66 * 68;            // [64][68]
    unsigned char* sTok = (unsigned char*)(sMP + 64 * 68);
    const int tid = threadIdx.x, bid = blockIdx.x;

    // int64 vs int32 token dtype detection (odd LE words of small int64 == 0)
    const int oddOr = seqs32[1] | seqs32[3] | seqs32[5] | seqs32[7] |
                      seqs32[9] | seqs32[11] | seqs32[13] | seqs32[15];
    const bool is64 = (oddOr == 0);

    for (int i = tid; i < 4096; i += 512)
        sS[(i >> 6) * 65 + (i & 63)] = g_S[i];
    {
        const float4* g = (const float4*)g_QP; float4* s = (float4*)sQP;
        for (int i = tid; i < 1122; i += 512) s[i] = g[i];
        g = (const float4*)g_MP; s = (float4*)sMP;
        for (int i = tid; i < 1088; i += 512) s[i] = g[i];
    }
    {
        const int base = bid * 128 * 24;
        for (int i = tid; i < 128 * 24; i += 512) {
            const int v = is64 ? seqs32[2 * (base + i)] : seqs32[base + i];
            sTok[i] = (unsigned char)v;
        }
    }
    const int jq = tid & 3;                // j-quarter: adjacent lanes differ
    const int bl = tid >> 2;               // local batch 0..127
    const int b  = bid * 128 + bl;
    const int qt = is64 ? qtok32[2 * b] : qtok32[b];
    __syncthreads();

    // ---- recurrence (integer-key argmax; validated R4-R10) ----
    int moff[8];
    {
        const unsigned char* myTok = sTok + bl * 24;
        int mt[8];
        #pragma unroll
        for (int s = 0; s < 8; s++) mt[s] = myTok[s];
        #pragma unroll
        for (int t = 8; t < 23; t++) {
            const int c = myTok[t];
            const float* Srow = sS + c * 65;
            unsigned key[8];
            #pragma unroll
            for (int s = 0; s < 8; s++) {
                const unsigned bits = __float_as_uint(Srow[mt[s]]);
                key[s] = (bits << 2) | (unsigned)(3 - (s & 3));
            }
            const unsigned a0 = max(max(key[0], key[1]), max(key[2], key[3]));
            const unsigned a1 = max(max(key[4], key[5]), max(key[6], key[7]));
            const int bi = ((a1 >> 2) > (a0 >> 2)) ? (4 + 3 - (int)(a1 & 3))
                                                   : (3 - (int)(a0 & 3));
            #pragma unroll
            for (int s = 0; s < 8; s++) if (bi == s) mt[s] = c;
        }
        #pragma unroll
        for (int s = 0; s < 8; s++) moff[s] = mt[s] * 68 + jq * 16;
    }

    // ---- h gather: this thread's 16 j's ----
    unsigned long long h[8];
    {
        const float* qp = sQP + qt * 68 + jq * 16;
        #pragma unroll
        for (int i = 0; i < 4; i++) {
            const ulonglong2 q = *(const ulonglong2*)(qp + 4 * i);
            h[2 * i] = q.x; h[2 * i + 1] = q.y;
        }
    }
    const unsigned long long E2 = pk2(0.125f, 0.125f);
    #pragma unroll
    for (int s = 0; s < 8; s++) {
        const float* mp = sMP + moff[s];
        #pragma unroll
        for (int i = 0; i < 4; i++) {
            const ulonglong2 m = *(const ulonglong2*)(mp + 4 * i);
            fma2(h[2 * i],     m.x, E2);
            fma2(h[2 * i + 1], m.y, E2);
        }
    }
    // relu + k-major store; each (row, 8-consecutive-batch) = full 32B sector
    float* ht = g_HT + (jq * 16) * BTOT + b;
    #pragma unroll
    for (int i = 0; i < 8; i++) {
        float lo, hi; upk2(h[i], lo, hi);
        ht[(2 * i)     * BTOT] = fmaxf(lo, 0.f);
        ht[(2 * i + 1) * BTOT] = fmaxf(hi, 0.f);
    }
}

// ============================ gemm: HT @ rw2 + rb2 ==========================
// grid 512 x 256; block tile 64b x 64c; warp 8b x 64c; thread 4b x 4c.
// Explicit software pipeline: k+1 loads issued before k's FFMA2 chain.
#define GEMM_SMEM_BYTES ((64 * 68 * 2 + 64) * 4)

__global__ void __launch_bounds__(256, 3) gemm_kernel(
    const float* __restrict__ rw2, const float* __restrict__ rb2,
    float* __restrict__ out)
{
    extern __shared__ float sm[];
    float* sHT = sm;                 // [64 k][68] (64 batches, padded)
    float* sW  = sm + 64 * 68;       // [64 k][68] (64 cols, padded)
    float* sRB = sW + 64 * 68;       // [64]
    const int tid = threadIdx.x, bid = blockIdx.x;
    const int b0 = bid * 64;

    for (int i = tid; i < 1024; i += 256) {
        const int r = i >> 4, c4 = i & 15;
        *(float4*)(sHT + r * 68 + c4 * 4) =
            *(const float4*)(g_HT + r * BTOT + b0 + c4 * 4);
        ((float4*)sW)[r * 17 + c4] = ((const float4*)rw2)[i];
    }
    if (tid < 16) ((float4*)sRB)[tid] = ((const float4*)rb2)[tid];
    __syncthreads();

    const int w = tid >> 5, lane = tid & 31;
    const int bg = lane >> 4;            // batch sub-group (0..1)
    const int cg = lane & 15;            // col group (0..15)
    const float* hrow = sHT + w * 8 + bg * 4;     // + k*68
    const float* wcol = sW + cg * 4;              // + k*68

    unsigned long long acc[8];           // 4 batches x 2 col-pairs
    {
        const ulonglong2 r0 = *(const ulonglong2*)(sRB + cg * 4);
        #pragma unroll
        for (int bb = 0; bb < 4; bb++) { acc[bb * 2] = r0.x; acc[bb * 2 + 1] = r0.y; }
    }

    // ---- software-pipelined k loop: loads for k+1 precede FMAs for k ----
    float4     hv = *(const float4*)(hrow);
    ulonglong2 wv = *(const ulonglong2*)(wcol);
    #pragma unroll 7
    for (int k = 0; k < 63; k++) {
        const float4     hn = *(const float4*)(hrow + (k + 1) * 68);
        const ulonglong2 wn = *(const ulonglong2*)(wcol + (k + 1) * 68);
        unsigned long long hb;
        hb = pk2(hv.x, hv.x); fma2(acc[0], hb, wv.x); fma2(acc[1], hb, wv.y);
        hb = pk2(hv.y, hv.y); fma2(acc[2], hb, wv.x); fma2(acc[3], hb, wv.y);
        hb = pk2(hv.z, hv.z); fma2(acc[4], hb, wv.x); fma2(acc[5], hb, wv.y);
        hb = pk2(hv.w, hv.w); fma2(acc[6], hb, wv.x); fma2(acc[7], hb, wv.y);
        hv = hn; wv = wn;
    }
    {
        unsigned long long hb;
        hb = pk2(hv.x, hv.x); fma2(acc[0], hb, wv.x); fma2(acc[1], hb, wv.y);
        hb = pk2(hv.y, hv.y); fma2(acc[2], hb, wv.x); fma2(acc[3], hb, wv.y);
        hb = pk2(hv.z, hv.z); fma2(acc[4], hb, wv.x); fma2(acc[5], hb, wv.y);
        hb = pk2(hv.w, hv.w); fma2(acc[6], hb, wv.x); fma2(acc[7], hb, wv.y);
    }

    const int gb0 = b0 + w * 8 + bg * 4;
    #pragma unroll
    for (int bb = 0; bb < 4; bb++) {
        float4 v;
        upk2(acc[bb * 2],     v.x, v.y);
        upk2(acc[bb * 2 + 1], v.z, v.w);
        *(float4*)(out + (gb0 + bb) * 64 + cg * 4) = v;
    }
}

// ============================== launch ======================================
extern "C" void kernel_launch(void* const* d_in, const int* in_sizes, int n_in,
                              void* d_out, int out_size)
{
    const int*   seqs  = (const int*)  d_in[0];
    const int*   qtok  = (const int*)  d_in[1];
    const float* embed = (const float*)d_in[2];
    const float* gw1   = (const float*)d_in[3];
    const float* gb1   = (const float*)d_in[4];
    const float* gw2   = (const float*)d_in[5];
    const float* gb2   = (const float*)d_in[6];
    const float* rw1   = (const float*)d_in[7];
    const float* rb1   = (const float*)d_in[8];
    const float* rw2   = (const float*)d_in[9];
    const float* rb2   = (const float*)d_in[10];

    cudaFuncSetAttribute(rh_kernel,
                         cudaFuncAttributeMaxDynamicSharedMemorySize,
                         RH_SMEM_BYTES);
    cudaFuncSetAttribute(gemm_kernel,
                         cudaFuncAttributeMaxDynamicSharedMemorySize,
                         GEMM_SMEM_BYTES);

    p0_kernel<<<49, 256>>>(embed, gw1, rw1, rb1);
    p1_kernel<<<32, 128>>>(gb1, gw2, gb2);
    rh_kernel<<<256, 512, RH_SMEM_BYTES>>>(seqs, qtok);
    gemm_kernel<<<512, 256, GEMM_SMEM_BYTES>>>(rw2, rb2, (float*)d_out);
}

// round 12
// speedup vs baseline: 1.1756x; 1.0509x over previous
#include <cuda_runtime.h>
#include <math.h>

// ---------------------------------------------------------------------------
// SelectiveModel: B=32768, T=23, H=64, SLOTS=8, VOCAB=64.
//
// Structural collapse: gating MLP -> S[64][64] sigmoid table (recurrence is
// pure integer state); readout L1 -> QP/MP tables; only the 64x64 L2 GEMM
// remains as real FP work.
//
// R12:
//   gemm: 512 thr / 128 batches / grid 256 -> 32 warps/SM, SINGLE wave,
//         R9's proven non-pipelined 4b x 4c inner loop, launch_bounds(512,2).
//   rh/p0/p1 identical to R11 (validated best).
// ---------------------------------------------------------------------------

#define BTOT 32768

__device__ float g_S  [64 * 64];
__device__ float g_QP [66 * 68];
__device__ float g_MP [64 * 68];
__device__ float g_ED [64 * 32];     // edot[c][j]
__device__ float g_MDT[32 * 64];     // mdot transposed [j][m]
__device__ float g_HT [64 * BTOT];   // k-major h

// ---------------- packed fp32x2 helpers -------------------------------------
__device__ __forceinline__ unsigned long long pk2(float lo, float hi) {
    unsigned long long r;
    asm("mov.b64 %0, {%1, %2};" : "=l"(r) : "f"(lo), "f"(hi));
    return r;
}
__device__ __forceinline__ void upk2(unsigned long long v, float& lo, float& hi) {
    asm("mov.b64 {%0, %1}, %2;" : "=f"(lo), "=f"(hi) : "l"(v));
}
__device__ __forceinline__ void fma2(unsigned long long& d,
                                     unsigned long long a, unsigned long long b) {
    asm("fma.rn.f32x2 %0, %1, %2, %0;" : "+l"(d) : "l"(a), "l"(b));
}

// ===================== P0: all independent dot products =====================
__global__ void p0_kernel(
    const float* __restrict__ embed, const float* __restrict__ gw1,
    const float* __restrict__ rw1,   const float* __restrict__ rb1)
{
    const int idx = blockIdx.x * 256 + threadIdx.x;
    if (idx < 4096) {
        const int r = idx >> 5, j = idx & 31;
        const float* e = embed + (r & 63) * 64;
        const float* w = gw1 + ((r >> 6) * 64) * 32 + j;
        float acc[4] = {0.f, 0.f, 0.f, 0.f};
        #pragma unroll
        for (int k0 = 0; k0 < 64; k0 += 8) {
            float wr[8], er[8];
            #pragma unroll
            for (int i = 0; i < 8; i++) { wr[i] = w[(k0 + i) * 32]; er[i] = e[k0 + i]; }
            #pragma unroll
            for (int i = 0; i < 8; i++) acc[i & 3] += er[i] * wr[i];
        }
        const float v = (acc[0] + acc[1]) + (acc[2] + acc[3]);
        if (r < 64) g_ED[r * 32 + j] = v;
        else        g_MDT[j * 64 + (r - 64)] = v;
    } else if (idx < 8320) {
        const int e2 = idx - 4096;
        const int r = e2 >> 6, j = e2 & 63;
        const float* e = embed + r * 64;
        const float* w = rw1 + j;
        float acc[4] = {rb1[j], 0.f, 0.f, 0.f};
        #pragma unroll
        for (int k0 = 0; k0 < 64; k0 += 8) {
            float wr[8], er[8];
            #pragma unroll
            for (int i = 0; i < 8; i++) { wr[i] = w[(k0 + i) * 64]; er[i] = e[k0 + i]; }
            #pragma unroll
            for (int i = 0; i < 8; i++) acc[i & 3] += er[i] * wr[i];
        }
        g_QP[r * 68 + j] = (acc[0] + acc[1]) + (acc[2] + acc[3]);
        if (j < 4) g_QP[r * 68 + 64 + j] = 0.f;
    } else if (idx < 12416) {
        const int e2 = idx - 8320;
        const int r = e2 >> 6, j = e2 & 63;
        const float* e = embed + r * 64;
        const float* w = rw1 + 64 * 64 + j;
        float acc[4] = {0.f, 0.f, 0.f, 0.f};
        #pragma unroll
        for (int k0 = 0; k0 < 64; k0 += 8) {
            float wr[8], er[8];
            #pragma unroll
            for (int i = 0; i < 8; i++) { wr[i] = w[(k0 + i) * 64]; er[i] = e[k0 + i]; }
            #pragma unroll
            for (int i = 0; i < 8; i++) acc[i & 3] += er[i] * wr[i];
        }
        g_MP[r * 68 + j] = (acc[0] + acc[1]) + (acc[2] + acc[3]);
        if (j < 4) g_MP[r * 68 + 64 + j] = 0.f;
    }
}

// ===================== P1: S table combine + sigmoid ========================
__global__ void p1_kernel(
    const float* __restrict__ gb1, const float* __restrict__ gw2,
    const float* __restrict__ gb2)
{
    const int idx = blockIdx.x * 128 + threadIdx.x;
    const int c = idx >> 6, m = idx & 63;
    const float* ed = g_ED + c * 32;
    float acc = gb2[0];
    #pragma unroll
    for (int j0 = 0; j0 < 32; j0 += 8) {
        float md[8], edv[8], gb[8], gw[8];
        #pragma unroll
        for (int i = 0; i < 8; i++) {
            md[i]  = g_MDT[(j0 + i) * 64 + m];
            edv[i] = ed[j0 + i];
            gb[i]  = gb1[j0 + i];
            gw[i]  = gw2[j0 + i];
        }
        #pragma unroll
        for (int i = 0; i < 8; i++)
            acc += fmaxf(edv[i] + md[i] + gb[i], 0.f) * gw[i];
    }
    g_S[c * 64 + m] = 1.f / (1.f + expf(-acc));
}

// ====================== rh: fused recurrence + h gather =====================
// grid 256 x 512; block = 128 batches. Unchanged from R11.
#define RH_SMEM_BYTES ((64 * 65 + 66 * 68 + 64 * 68) * 4 + 128 * 24)

__global__ void __launch_bounds__(512, 2) rh_kernel(
    const int* __restrict__ seqs32, const int* __restrict__ qtok32)
{
    extern __shared__ float sm[];
    float* sS  = sm;                       // [64][65]
    float* sQP = sS + 64 * 65;             // [66][68]
    float* sMP = sQP + 66 * 68;            // [64][68]
    unsigned char* sTok = (unsigned char*)(sMP + 64 * 68);
    const int tid = threadIdx.x, bid = blockIdx.x;

    // int64 vs int32 token dtype detection (odd LE words of small int64 == 0)
    const int oddOr = seqs32[1] | seqs32[3] | seqs32[5] | seqs32[7] |
                      seqs32[9] | seqs32[11] | seqs32[13] | seqs32[15];
    const bool is64 = (oddOr == 0);

    for (int i = tid; i < 4096; i += 512)
        sS[(i >> 6) * 65 + (i & 63)] = g_S[i];
    {
        const float4* g = (const float4*)g_QP; float4* s = (float4*)sQP;
        for (int i = tid; i < 1122; i += 512) s[i] = g[i];
        g = (const float4*)g_MP; s = (float4*)sMP;
        for (int i = tid; i < 1088; i += 512) s[i] = g[i];
    }
    {
        const int base = bid * 128 * 24;
        for (int i = tid; i < 128 * 24; i += 512) {
            const int v = is64 ? seqs32[2 * (base + i)] : seqs32[base + i];
            sTok[i] = (unsigned char)v;
        }
    }
    const int jq = tid & 3;                // j-quarter: adjacent lanes differ
    const int bl = tid >> 2;               // local batch 0..127
    const int b  = bid * 128 + bl;
    const int qt = is64 ? qtok32[2 * b] : qtok32[b];
    __syncthreads();

    // ---- recurrence (integer-key argmax; validated R4-R11) ----
    int moff[8];
    {
        const unsigned char* myTok = sTok + bl * 24;
        int mt[8];
        #pragma unroll
        for (int s = 0; s < 8; s++) mt[s] = myTok[s];
        #pragma unroll
        for (int t = 8; t < 23; t++) {
            const int c = myTok[t];
            const float* Srow = sS + c * 65;
            unsigned key[8];
            #pragma unroll
            for (int s = 0; s < 8; s++) {
                const unsigned bits = __float_as_uint(Srow[mt[s]]);
                key[s] = (bits << 2) | (unsigned)(3 - (s & 3));
            }
            const unsigned a0 = max(max(key[0], key[1]), max(key[2], key[3]));
            const unsigned a1 = max(max(key[4], key[5]), max(key[6], key[7]));
            const int bi = ((a1 >> 2) > (a0 >> 2)) ? (4 + 3 - (int)(a1 & 3))
                                                   : (3 - (int)(a0 & 3));
            #pragma unroll
            for (int s = 0; s < 8; s++) if (bi == s) mt[s] = c;
        }
        #pragma unroll
        for (int s = 0; s < 8; s++) moff[s] = mt[s] * 68 + jq * 16;
    }

    // ---- h gather: this thread's 16 j's ----
    unsigned long long h[8];
    {
        const float* qp = sQP + qt * 68 + jq * 16;
        #pragma unroll
        for (int i = 0; i < 4; i++) {
            const ulonglong2 q = *(const ulonglong2*)(qp + 4 * i);
            h[2 * i] = q.x; h[2 * i + 1] = q.y;
        }
    }
    const unsigned long long E2 = pk2(0.125f, 0.125f);
    #pragma unroll
    for (int s = 0; s < 8; s++) {
        const float* mp = sMP + moff[s];
        #pragma unroll
        for (int i = 0; i < 4; i++) {
            const ulonglong2 m = *(const ulonglong2*)(mp + 4 * i);
            fma2(h[2 * i],     m.x, E2);
            fma2(h[2 * i + 1], m.y, E2);
        }
    }
    // relu + k-major store; each (row, 8-consecutive-batch) = full 32B sector
    float* ht = g_HT + (jq * 16) * BTOT + b;
    #pragma unroll
    for (int i = 0; i < 8; i++) {
        float lo, hi; upk2(h[i], lo, hi);
        ht[(2 * i)     * BTOT] = fmaxf(lo, 0.f);
        ht[(2 * i + 1) * BTOT] = fmaxf(hi, 0.f);
    }
}

// ============================ gemm: HT @ rw2 + rb2 ==========================
// grid 256 x 512; block tile 128b x 64c; warp 8b x 64c; thread 4b x 4c.
// Single wave (256 blocks <= 2/SM * 148), 32 warps/SM.
#define GEMM_SMEM_BYTES ((64 * 132 + 64 * 68 + 64) * 4)

__global__ void __launch_bounds__(512, 2) gemm_kernel(
    const float* __restrict__ rw2, const float* __restrict__ rb2,
    float* __restrict__ out)
{
    extern __shared__ float sm[];
    float* sHT = sm;                 // [64 k][132] (128 batches, padded)
    float* sW  = sm + 64 * 132;      // [64 k][68]  (64 cols, padded)
    float* sRB = sW + 64 * 68;       // [64]
    const int tid = threadIdx.x, bid = blockIdx.x;
    const int b0 = bid * 128;

    for (int i = tid; i < 2048; i += 512) {          // HT tile: 64 x 128
        const int r = i >> 5, c4 = i & 31;
        *(float4*)(sHT + r * 132 + c4 * 4) =
            *(const float4*)(g_HT + r * BTOT + b0 + c4 * 4);
    }
    for (int i = tid; i < 1024; i += 512)            // W re-padded 64 -> 68
        ((float4*)sW)[(i >> 4) * 17 + (i & 15)] = ((const float4*)rw2)[i];
    if (tid < 16) ((float4*)sRB)[tid] = ((const float4*)rb2)[tid];
    __syncthreads();

    const int w = tid >> 5, lane = tid & 31;         // 16 warps x 8 batches
    const int bg = lane >> 4;            // batch sub-group (0..1)
    const int cg = lane & 15;            // col group (0..15)
    const float* hrow = sHT + w * 8 + bg * 4;        // + k*132
    const float* wcol = sW + cg * 4;                 // + k*68

    unsigned long long acc[8];           // 4 batches x 2 col-pairs
    {
        const ulonglong2 r0 = *(const ulonglong2*)(sRB + cg * 4);
        #pragma unroll
        for (int bb = 0; bb < 4; bb++) { acc[bb * 2] = r0.x; acc[bb * 2 + 1] = r0.y; }
    }
    #pragma unroll 8
    for (int k = 0; k < 64; k++) {
        const float4 hv     = *(const float4*)(hrow + k * 132);
        const ulonglong2 wv = *(const ulonglong2*)(wcol + k * 68);
        unsigned long long hb;
        hb = pk2(hv.x, hv.x); fma2(acc[0], hb, wv.x); fma2(acc[1], hb, wv.y);
        hb = pk2(hv.y, hv.y); fma2(acc[2], hb, wv.x); fma2(acc[3], hb, wv.y);
        hb = pk2(hv.z, hv.z); fma2(acc[4], hb, wv.x); fma2(acc[5], hb, wv.y);
        hb = pk2(hv.w, hv.w); fma2(acc[6], hb, wv.x); fma2(acc[7], hb, wv.y);
    }

    const int gb0 = b0 + w * 8 + bg * 4;
    #pragma unroll
    for (int bb = 0; bb < 4; bb++) {
        float4 v;
        upk2(acc[bb * 2],     v.x, v.y);
        upk2(acc[bb * 2 + 1], v.z, v.w);
        *(float4*)(out + (gb0 + bb) * 64 + cg * 4) = v;
    }
}

// ============================== launch ======================================
extern "C" void kernel_launch(void* const* d_in, const int* in_sizes, int n_in,
                              void* d_out, int out_size)
{
    const int*   seqs  = (const int*)  d_in[0];
    const int*   qtok  = (const int*)  d_in[1];
    const float* embed = (const float*)d_in[2];
    const float* gw1   = (const float*)d_in[3];
    const float* gb1   = (const float*)d_in[4];
    const float* gw2   = (const float*)d_in[5];
    const float* gb2   = (const float*)d_in[6];
    const float* rw1   = (const float*)d_in[7];
    const float* rb1   = (const float*)d_in[8];
    const float* rw2   = (const float*)d_in[9];
    const float* rb2   = (const float*)d_in[10];

    cudaFuncSetAttribute(rh_kernel,
                         cudaFuncAttributeMaxDynamicSharedMemorySize,
                         RH_SMEM_BYTES);
    cudaFuncSetAttribute(gemm_kernel,
                         cudaFuncAttributeMaxDynamicSharedMemorySize,
                         GEMM_SMEM_BYTES);

    p0_kernel<<<49, 256>>>(embed, gw1, rw1, rb1);
    p1_kernel<<<32, 128>>>(gb1, gw2, gb2);
    rh_kernel<<<256, 512, RH_SMEM_BYTES>>>(seqs, qtok);
    gemm_kernel<<<256, 512, GEMM_SMEM_BYTES>>>(rw2, rb2, (float*)d_out);
}